// round 4
// baseline (speedup 1.0000x reference)
#include <cuda_runtime.h>
#include <math.h>
#include <stdint.h>

#define NGRAPH 32
#define NNODE  1024
#define CDIM   64
#define KTOP   16
#define NROWS  (NGRAPH * NNODE)            // 32768
#define OUT_ELEMS (NROWS * CDIM)           // 2097152
#define ROWS_OFF  OUT_ELEMS
#define COLS_OFF  (OUT_ELEMS + NROWS * KTOP)

__device__ float g_sq[NROWS];

// ---------------------------------------------------------------------------
// Encoder: out[32768,64] = x[32768,128] @ W[128,64] + b   (verified, unchanged)
// ---------------------------------------------------------------------------
__global__ void __launch_bounds__(256) enc_kernel(const float* __restrict__ x,
                                                  const float* __restrict__ W,
                                                  const float* __restrict__ b,
                                                  float* __restrict__ out) {
    __shared__ float sWt[64 * 132];   // W transposed [c][k], stride 132
    __shared__ float sX[16 * 128];    // 16-row strip of x
    int tid = threadIdx.x;
    int i0 = blockIdx.x * 16;

    for (int idx = tid; idx < 128 * 64; idx += 256) {
        int k = idx >> 6, c = idx & 63;
        sWt[c * 132 + k] = W[idx];
    }
    for (int idx = tid; idx < 16 * 128 / 4; idx += 256) {
        ((float4*)sX)[idx] = ((const float4*)(x + (size_t)i0 * 128))[idx];
    }
    __syncthreads();

    int c = tid & 63, ty = tid >> 6;
    float acc[4] = {0.f, 0.f, 0.f, 0.f};
    const float4* wt = (const float4*)(sWt + c * 132);
#pragma unroll
    for (int k4 = 0; k4 < 32; k4++) {
        float4 wv = wt[k4];
#pragma unroll
        for (int rr = 0; rr < 4; rr++) {
            float4 xv = ((const float4*)(sX + (ty + rr * 4) * 128))[k4];
            acc[rr] += xv.x * wv.x + xv.y * wv.y + xv.z * wv.z + xv.w * wv.w;
        }
    }
    float bc = b[c];
#pragma unroll
    for (int rr = 0; rr < 4; rr++) {
        out[(size_t)(i0 + ty + rr * 4) * 64 + c] = acc[rr] + bc;
    }
}

// ---------------------------------------------------------------------------
// Row squared norms (verified, unchanged)
// ---------------------------------------------------------------------------
__global__ void __launch_bounds__(256) sq_kernel(const float* __restrict__ out) {
    int warp = (blockIdx.x * blockDim.x + threadIdx.x) >> 5;
    int lane = threadIdx.x & 31;
    if (warp >= NROWS) return;
    const float* p = out + (size_t)warp * 64;
    float a = p[lane], c = p[lane + 32];
    float s = a * a + c * c;
#pragma unroll
    for (int o = 16; o; o >>= 1) s += __shfl_xor_sync(0xffffffffu, s, o);
    if (lane == 0) g_sq[warp] = s;
}

// ---------------------------------------------------------------------------
// JAX threefry2x32, key (0,1), partitionable counter mode (verified R3).
// ---------------------------------------------------------------------------
__device__ __forceinline__ uint32_t threefry_bits_k01(uint32_t e) {
    const uint32_t ks0 = 0u, ks1 = 1u, ks2 = 0x1BD11BDBu;
    uint32_t x0 = 0u + ks0;
    uint32_t x1 = e + ks1;
#define TF_ROUND(r) { x0 += x1; x1 = __funnelshift_l(x1, x1, (r)); x1 ^= x0; }
    TF_ROUND(13) TF_ROUND(15) TF_ROUND(26) TF_ROUND(6)
    x0 += ks1; x1 += ks2 + 1u;
    TF_ROUND(17) TF_ROUND(29) TF_ROUND(16) TF_ROUND(24)
    x0 += ks2; x1 += ks0 + 2u;
    TF_ROUND(13) TF_ROUND(15) TF_ROUND(26) TF_ROUND(6)
    x0 += ks0; x1 += ks1 + 3u;
    TF_ROUND(17) TF_ROUND(29) TF_ROUND(16) TF_ROUND(24)
    x0 += ks1; x1 += ks2 + 4u;
    TF_ROUND(13) TF_ROUND(15) TF_ROUND(26) TF_ROUND(6)
    x0 += ks2; x1 += ks0 + 5u;
#undef TF_ROUND
    return x0 ^ x1;
}

// gumbel = -log(-log(max(tiny, f+tiny))). Inner -log(u) via log1pf(u-1):
// f-1 is EXACT in fp32, log1pf keeps absolute accuracy as u->1 (the region
// top-k actually selects). f==0 -> u=tiny -> -log(u) = 87.33654.
// Outer log via __logf (abs err ~1e-7, well inside the rank-flip budget).
__device__ __forceinline__ float gumbel_from_bits(uint32_t bits) {
    float f = __uint_as_float((bits >> 9) | 0x3f800000u) - 1.0f;
    float w = (f == 0.0f) ? 87.3365402f : -log1pf(f - 1.0f);
    return -__logf(w);
}

// ---------------------------------------------------------------------------
// Fused: pairwise dist + logits + gumbel + top-16 per row.
// Block = (graph g, 32-row i-strip), 256 threads, grid (32, 32).
// j tiled by 128; thread computes a 4i x 4j dot tile (8 LDS.128 / 64 FFMA).
// ---------------------------------------------------------------------------
#define TI 32
#define TJ 128
#define SSTRIDE 68    // floats; 17 16B-units/row (odd) -> conflict-free LDS.128

// shared layout in floats
#define SM_SA     0                        // [32][68]   = 2176
#define SM_SB     2176                     // [128][68]  = 8704
#define SM_SQI    10880                    // [32]
#define SM_SQJ    10912                    // [128]
#define SM_THR    11040                    // [32]
#define SM_TOPV   11072                    // [32][16]   = 512
#define SM_CANDV  11584                    // [32][128]  = 4096
#define SM_CANDI  15680                    // [32][128] int
#define SM_TOPI   19776                    // [32][16] int
#define SM_CNT    20288                    // [32] int
#define SM_TOTALF 20320
#define SM_BYTES  (SM_TOTALF * 4)          // 81280 B -> 2 blocks/SM

__global__ void __launch_bounds__(256) dgm_kernel(float* __restrict__ buf,
                                                  const float* __restrict__ tptr) {
    extern __shared__ float sm[];
    float* sA    = sm + SM_SA;
    float* sB    = sm + SM_SB;
    float* sqI   = sm + SM_SQI;
    float* sqJ   = sm + SM_SQJ;
    float* thr   = sm + SM_THR;
    float* topV  = sm + SM_TOPV;
    float* candV = sm + SM_CANDV;
    int*   candI = (int*)(sm + SM_CANDI);
    int*   topI  = (int*)(sm + SM_TOPI);
    int*   cnt   = (int*)(sm + SM_CNT);

    const float* h = buf;
    int tid = threadIdx.x;
    int g   = blockIdx.x;
    int i0  = blockIdx.y * TI;
    int gbase = g * NNODE;

    // ---- init ----
    for (int idx = tid; idx < TI * 16; idx += 256) {
        int r = idx >> 4, k4 = idx & 15;
        *(float4*)(sA + r * SSTRIDE + k4 * 4) =
            ((const float4*)(h + (size_t)(gbase + i0 + r) * 64))[k4];
    }
    if (tid < TI) {
        sqI[tid] = g_sq[gbase + i0 + tid];
        thr[tid] = -INFINITY;
        cnt[tid] = 0;
    }
    for (int idx = tid; idx < TI * KTOP; idx += 256) { topV[idx] = -INFINITY; topI[idx] = 0; }

    float nT = -(*tptr);
    int tx = tid & 31;      // j-group: cols tx + 32*jj
    int ty = tid >> 5;      // i-group: rows ty*4 + ii

    for (int jt = 0; jt < NNODE / TJ; jt++) {
        int j0 = jt * TJ;
        for (int idx = tid; idx < TJ * 16; idx += 256) {
            int r = idx >> 4, k4 = idx & 15;
            *(float4*)(sB + r * SSTRIDE + k4 * 4) =
                ((const float4*)(h + (size_t)(gbase + j0 + r) * 64))[k4];
        }
        if (tid < TJ) sqJ[tid] = g_sq[gbase + j0 + tid];
        __syncthreads();

        // ---- 4x4 register-tiled dots ----
        float acc[4][4];
#pragma unroll
        for (int ii = 0; ii < 4; ii++)
#pragma unroll
            for (int jj = 0; jj < 4; jj++) acc[ii][jj] = 0.f;

        const float* pA = sA + (ty * 4) * SSTRIDE;
        const float* pB = sB + tx * SSTRIDE;
#pragma unroll
        for (int k4 = 0; k4 < 16; k4++) {
            float4 jf0 = *(const float4*)(pB + (0 * 32) * SSTRIDE + k4 * 4);
            float4 jf1 = *(const float4*)(pB + (1 * 32) * SSTRIDE + k4 * 4);
            float4 jf2 = *(const float4*)(pB + (2 * 32) * SSTRIDE + k4 * 4);
            float4 jf3 = *(const float4*)(pB + (3 * 32) * SSTRIDE + k4 * 4);
#pragma unroll
            for (int ii = 0; ii < 4; ii++) {
                float4 af = *(const float4*)(pA + ii * SSTRIDE + k4 * 4);
                acc[ii][0] += af.x * jf0.x + af.y * jf0.y + af.z * jf0.z + af.w * jf0.w;
                acc[ii][1] += af.x * jf1.x + af.y * jf1.y + af.z * jf1.z + af.w * jf1.w;
                acc[ii][2] += af.x * jf2.x + af.y * jf2.y + af.z * jf2.z + af.w * jf2.w;
                acc[ii][3] += af.x * jf3.x + af.y * jf3.y + af.z * jf3.z + af.w * jf3.w;
            }
        }

        // ---- per-tile scalars to registers ----
        float thrR[4], sqi[4], sqj[4];
#pragma unroll
        for (int ii = 0; ii < 4; ii++) { thrR[ii] = thr[ty * 4 + ii]; sqi[ii] = sqI[ty * 4 + ii]; }
#pragma unroll
        for (int jj = 0; jj < 4; jj++) sqj[jj] = sqJ[jj * 32 + tx];

        // ---- logits + gumbel + threshold filter ----
#pragma unroll
        for (int ii = 0; ii < 4; ii++) {
            int li = ty * 4 + ii;
            uint32_t ebase = ((uint32_t)g << 20) + ((uint32_t)(i0 + li) << 10)
                             + (uint32_t)(j0 + tx);
#pragma unroll
            for (int jj = 0; jj < 4; jj++) {
                float s  = __fadd_rn(sqi[ii], sqj[jj]);
                float d  = __fadd_rn(s, -__fmul_rn(2.0f, acc[ii][jj]));
                float lg = __expf(__fmul_rn(nT, d));
                float v  = lg + gumbel_from_bits(threefry_bits_k01(ebase + jj * 32u));
                if (v > thrR[ii]) {
                    int p = atomicAdd(&cnt[li], 1);
                    candV[li * TJ + p] = v;
                    candI[li * TJ + p] = j0 + jj * 32 + tx;
                }
            }
        }
        __syncthreads();

        // ---- leaders merge candidates into sorted top-16, raise threshold ----
        if (tid < TI) {
            int r = tid, c = cnt[r];
            float* tv = topV + r * KTOP;
            int*   ti = topI + r * KTOP;
            for (int m = 0; m < c; m++) {
                float v = candV[r * TJ + m];
                if (v > tv[KTOP - 1]) {
                    int id = candI[r * TJ + m];
                    int p = KTOP - 1;
                    while (p > 0 && tv[p - 1] < v) {
                        tv[p] = tv[p - 1]; ti[p] = ti[p - 1]; p--;
                    }
                    tv[p] = v; ti[p] = id;
                }
            }
            cnt[r] = 0;
            thr[r] = tv[KTOP - 1];
        }
        __syncthreads();
    }

    // ---- write edges (indices as float) ----
    if (tid < TI) {
        int grow = gbase + i0 + tid;
        size_t base = (size_t)grow * KTOP;
        float rowv = (float)grow;
#pragma unroll
        for (int k = 0; k < KTOP; k++) {
            buf[ROWS_OFF + base + k] = rowv;
            buf[COLS_OFF + base + k] = (float)(gbase + topI[tid * KTOP + k]);
        }
    }
}

// ---------------------------------------------------------------------------
extern "C" void kernel_launch(void* const* d_in, const int* in_sizes, int n_in,
                              void* d_out, int out_size) {
    const float* x    = (const float*)d_in[0];
    const float* W    = (const float*)d_in[1];
    const float* b    = (const float*)d_in[2];
    const float* temp = (const float*)d_in[3];
    float* out = (float*)d_out;

    enc_kernel<<<NROWS / 16, 256>>>(x, W, b, out);
    sq_kernel<<<NROWS / 8, 256>>>(out);
    cudaFuncSetAttribute(dgm_kernel, cudaFuncAttributeMaxDynamicSharedMemorySize, SM_BYTES);
    dgm_kernel<<<dim3(NGRAPH, NNODE / TI), 256, SM_BYTES>>>(out, temp);
}

// round 5
// speedup vs baseline: 1.5834x; 1.5834x over previous
#include <cuda_runtime.h>
#include <math.h>
#include <stdint.h>

#define NGRAPH 32
#define NNODE  1024
#define CDIM   64
#define KTOP   16
#define NROWS  (NGRAPH * NNODE)            // 32768
#define OUT_ELEMS (NROWS * CDIM)           // 2097152
#define ROWS_OFF  OUT_ELEMS
#define COLS_OFF  (OUT_ELEMS + NROWS * KTOP)

__device__ float g_sq[NROWS];

// ---------------------------------------------------------------------------
// Encoder + fused row squared-norms.
// out[32768,64] = x[32768,128] @ W[128,64] + b ; g_sq[r] = sum_c out[r,c]^2
// ---------------------------------------------------------------------------
__global__ void __launch_bounds__(256) enc_kernel(const float* __restrict__ x,
                                                  const float* __restrict__ W,
                                                  const float* __restrict__ b,
                                                  float* __restrict__ out) {
    __shared__ float sWt[64 * 132];   // W transposed [c][k], stride 132
    __shared__ float sX[16 * 128];    // 16-row strip of x
    __shared__ float red[4][4][2];    // [ty][rr][warp-half] partial sq sums
    int tid = threadIdx.x;
    int i0 = blockIdx.x * 16;

    for (int idx = tid; idx < 128 * 64; idx += 256) {
        int k = idx >> 6, c = idx & 63;
        sWt[c * 132 + k] = W[idx];
    }
    for (int idx = tid; idx < 16 * 128 / 4; idx += 256) {
        ((float4*)sX)[idx] = ((const float4*)(x + (size_t)i0 * 128))[idx];
    }
    __syncthreads();

    int c = tid & 63, ty = tid >> 6;
    float acc[4] = {0.f, 0.f, 0.f, 0.f};
    const float4* wt = (const float4*)(sWt + c * 132);
#pragma unroll
    for (int k4 = 0; k4 < 32; k4++) {
        float4 wv = wt[k4];
#pragma unroll
        for (int rr = 0; rr < 4; rr++) {
            float4 xv = ((const float4*)(sX + (ty + rr * 4) * 128))[k4];
            acc[rr] += xv.x * wv.x + xv.y * wv.y + xv.z * wv.z + xv.w * wv.w;
        }
    }
    float bc = b[c];
    float sq[4];
#pragma unroll
    for (int rr = 0; rr < 4; rr++) {
        float val = acc[rr] + bc;
        out[(size_t)(i0 + ty + rr * 4) * 64 + c] = val;
        sq[rr] = val * val;
    }
    // reduce sq over the 64 c-threads (2 warps) per (ty, rr)
#pragma unroll
    for (int rr = 0; rr < 4; rr++) {
#pragma unroll
        for (int o = 16; o; o >>= 1) sq[rr] += __shfl_xor_sync(0xffffffffu, sq[rr], o);
    }
    if ((tid & 31) == 0) {
        int half = (tid >> 5) & 1;
#pragma unroll
        for (int rr = 0; rr < 4; rr++) red[ty][rr][half] = sq[rr];
    }
    __syncthreads();
    if (tid < 16) {
        int tty = tid >> 2, rr = tid & 3;
        g_sq[i0 + tty + rr * 4] = red[tty][rr][0] + red[tty][rr][1];
    }
}

// ---------------------------------------------------------------------------
// JAX threefry2x32, key (0,1), partitionable counter mode (verified R3).
// ---------------------------------------------------------------------------
__device__ __forceinline__ uint32_t threefry_bits_k01(uint32_t e) {
    const uint32_t ks0 = 0u, ks1 = 1u, ks2 = 0x1BD11BDBu;
    uint32_t x0 = 0u + ks0;
    uint32_t x1 = e + ks1;
#define TF_ROUND(r) { x0 += x1; x1 = __funnelshift_l(x1, x1, (r)); x1 ^= x0; }
    TF_ROUND(13) TF_ROUND(15) TF_ROUND(26) TF_ROUND(6)
    x0 += ks1; x1 += ks2 + 1u;
    TF_ROUND(17) TF_ROUND(29) TF_ROUND(16) TF_ROUND(24)
    x0 += ks2; x1 += ks0 + 2u;
    TF_ROUND(13) TF_ROUND(15) TF_ROUND(26) TF_ROUND(6)
    x0 += ks0; x1 += ks1 + 3u;
    TF_ROUND(17) TF_ROUND(29) TF_ROUND(16) TF_ROUND(24)
    x0 += ks1; x1 += ks2 + 4u;
    TF_ROUND(13) TF_ROUND(15) TF_ROUND(26) TF_ROUND(6)
    x0 += ks2; x1 += ks0 + 5u;
#undef TF_ROUND
    return x0 ^ x1;
}

// ---------------------------------------------------------------------------
// Fused: pairwise dist + logits + gumbel + top-16 per row.
// Block = (graph g, 32-row i-strip), 256 threads, grid (32, 32), 3 blocks/SM.
// Bit-level noise prefilter: element survives only if its uniform mantissa
// bits exceed the per-row cutoff derived from the running threshold.
// ---------------------------------------------------------------------------
#define TI 32
#define TJ 128
#define CAP 96
#define SSTRIDE 68    // floats; odd 16B-unit stride -> conflict-free LDS.128
#define THR0 2.0f     // phantom init threshold (v_16th of 1024 >> 2 w.p. ~1)
#define LGMAX 1.001f  // rigorous upper bound on exp(-T*d) incl. rounding

// shared layout in floats
#define SM_SA     0                        // [32][68]   = 2176
#define SM_SB     2176                     // [128][68]  = 8704
#define SM_SQI    10880                    // [32]
#define SM_SQJ    10912                    // [128]
#define SM_THR    11040                    // [32]
#define SM_CUTB   11072                    // [32] uint
#define SM_TOPV   11104                    // [32][16]   = 512
#define SM_CANDV  11616                    // [32][96]   = 3072
#define SM_CANDI  14688                    // [32][96] int
#define SM_TOPI   17760                    // [32][16] int
#define SM_CNT    18272                    // [32] int
#define SM_TOTALF 18304
#define SM_BYTES  (SM_TOTALF * 4)          // 73216 B -> 3 blocks/SM

__device__ __forceinline__ uint32_t cut_bits_from_thr(float thr) {
    // f-cutoff: v > thr requires gumbel > thr - LGMAX, i.e.
    // f > exp(-exp(-(thr - LGMAX))). Small downward slack keeps it conservative.
    float fcut = __expf(-__expf(-(thr - LGMAX))) - 2e-7f;
    return __float_as_uint(1.0f + fcut);   // compare in bit space vs (bits>>9)|0x3f800000
}

__global__ void __launch_bounds__(256, 3) dgm_kernel(float* __restrict__ buf,
                                                     const float* __restrict__ tptr) {
    extern __shared__ float sm[];
    float* sA    = sm + SM_SA;
    float* sB    = sm + SM_SB;
    float* sqI   = sm + SM_SQI;
    float* sqJ   = sm + SM_SQJ;
    float* thr   = sm + SM_THR;
    uint32_t* cutb = (uint32_t*)(sm + SM_CUTB);
    float* topV  = sm + SM_TOPV;
    float* candV = sm + SM_CANDV;
    int*   candI = (int*)(sm + SM_CANDI);
    int*   topI  = (int*)(sm + SM_TOPI);
    int*   cnt   = (int*)(sm + SM_CNT);

    const float* h = buf;
    int tid = threadIdx.x;
    int g   = blockIdx.x;
    int i0  = blockIdx.y * TI;
    int gbase = g * NNODE;

    // ---- init ----
    for (int idx = tid; idx < TI * 16; idx += 256) {
        int r = idx >> 4, k4 = idx & 15;
        *(float4*)(sA + r * SSTRIDE + k4 * 4) =
            ((const float4*)(h + (size_t)(gbase + i0 + r) * 64))[k4];
    }
    if (tid < TI) {
        sqI[tid] = g_sq[gbase + i0 + tid];
        thr[tid] = THR0;
        cutb[tid] = cut_bits_from_thr(THR0);
        cnt[tid] = 0;
    }
    for (int idx = tid; idx < TI * KTOP; idx += 256) { topV[idx] = -INFINITY; topI[idx] = 0; }

    float nT = -(*tptr);
    int tx = tid & 31;      // j-cols: tx + 32*jj
    int ty = tid >> 5;      // i-rows: ty*4 + ii

    for (int jt = 0; jt < NNODE / TJ; jt++) {
        int j0 = jt * TJ;
        for (int idx = tid; idx < TJ * 16; idx += 256) {
            int r = idx >> 4, k4 = idx & 15;
            *(float4*)(sB + r * SSTRIDE + k4 * 4) =
                ((const float4*)(h + (size_t)(gbase + j0 + r) * 64))[k4];
        }
        if (tid < TJ) sqJ[tid] = g_sq[gbase + j0 + tid];
        __syncthreads();

        // ---- 4x4 register-tiled dots ----
        float acc[4][4];
#pragma unroll
        for (int ii = 0; ii < 4; ii++)
#pragma unroll
            for (int jj = 0; jj < 4; jj++) acc[ii][jj] = 0.f;

        const float* pA = sA + (ty * 4) * SSTRIDE;
        const float* pB = sB + tx * SSTRIDE;
#pragma unroll
        for (int k4 = 0; k4 < 16; k4++) {
            float4 jf0 = *(const float4*)(pB + (0 * 32) * SSTRIDE + k4 * 4);
            float4 jf1 = *(const float4*)(pB + (1 * 32) * SSTRIDE + k4 * 4);
            float4 jf2 = *(const float4*)(pB + (2 * 32) * SSTRIDE + k4 * 4);
            float4 jf3 = *(const float4*)(pB + (3 * 32) * SSTRIDE + k4 * 4);
#pragma unroll
            for (int ii = 0; ii < 4; ii++) {
                float4 af = *(const float4*)(pA + ii * SSTRIDE + k4 * 4);
                acc[ii][0] += af.x * jf0.x + af.y * jf0.y + af.z * jf0.z + af.w * jf0.w;
                acc[ii][1] += af.x * jf1.x + af.y * jf1.y + af.z * jf1.z + af.w * jf1.w;
                acc[ii][2] += af.x * jf2.x + af.y * jf2.y + af.z * jf2.z + af.w * jf2.w;
                acc[ii][3] += af.x * jf3.x + af.y * jf3.y + af.z * jf3.z + af.w * jf3.w;
            }
        }

        // ---- per-row scalars to registers ----
        float thrR[4], sqi[4], sqj[4];
        uint32_t cutR[4];
#pragma unroll
        for (int ii = 0; ii < 4; ii++) {
            thrR[ii] = thr[ty * 4 + ii];
            sqi[ii]  = sqI[ty * 4 + ii];
            cutR[ii] = cutb[ty * 4 + ii];
        }
#pragma unroll
        for (int jj = 0; jj < 4; jj++) sqj[jj] = sqJ[jj * 32 + tx];

        // ---- noise-prefiltered epilogue ----
#pragma unroll
        for (int ii = 0; ii < 4; ii++) {
            int li = ty * 4 + ii;
            uint32_t ebase = ((uint32_t)g << 20) + ((uint32_t)(i0 + li) << 10)
                             + (uint32_t)(j0 + tx);
#pragma unroll
            for (int jj = 0; jj < 4; jj++) {
                uint32_t bits = threefry_bits_k01(ebase + jj * 32u);
                uint32_t m = (bits >> 9) | 0x3f800000u;
                if (m > cutR[ii]) {
                    // exact path (survivors only)
                    float f   = __uint_as_float(m) - 1.0f;
                    float gum = -__logf(-log1pf(f - 1.0f));
                    float s   = __fadd_rn(sqi[ii], sqj[jj]);
                    float d   = __fadd_rn(s, -__fmul_rn(2.0f, acc[ii][jj]));
                    float lg  = __expf(__fmul_rn(nT, d));
                    float v   = lg + gum;
                    if (v > thrR[ii]) {
                        int p = atomicAdd(&cnt[li], 1);
                        if (p < CAP) {
                            candV[li * CAP + p] = v;
                            candI[li * CAP + p] = j0 + jj * 32 + tx;
                        }
                    }
                }
            }
        }
        __syncthreads();

        // ---- leaders merge candidates, raise threshold + bit cutoff ----
        if (tid < TI) {
            int r = tid, c = min(cnt[r], CAP);
            float* tv = topV + r * KTOP;
            int*   ti = topI + r * KTOP;
            for (int m = 0; m < c; m++) {
                float v = candV[r * CAP + m];
                if (v > tv[KTOP - 1]) {
                    int id = candI[r * CAP + m];
                    int p = KTOP - 1;
                    while (p > 0 && tv[p - 1] < v) {
                        tv[p] = tv[p - 1]; ti[p] = ti[p - 1]; p--;
                    }
                    tv[p] = v; ti[p] = id;
                }
            }
            cnt[r] = 0;
            float nthr = fmaxf(tv[KTOP - 1], THR0);
            thr[r] = nthr;
            cutb[r] = cut_bits_from_thr(nthr);
        }
        __syncthreads();
    }

    // ---- write edges (indices as float) ----
    if (tid < TI) {
        int grow = gbase + i0 + tid;
        size_t base = (size_t)grow * KTOP;
        float rowv = (float)grow;
#pragma unroll
        for (int k = 0; k < KTOP; k++) {
            buf[ROWS_OFF + base + k] = rowv;
            buf[COLS_OFF + base + k] = (float)(gbase + topI[tid * KTOP + k]);
        }
    }
}

// ---------------------------------------------------------------------------
extern "C" void kernel_launch(void* const* d_in, const int* in_sizes, int n_in,
                              void* d_out, int out_size) {
    const float* x    = (const float*)d_in[0];
    const float* W    = (const float*)d_in[1];
    const float* b    = (const float*)d_in[2];
    const float* temp = (const float*)d_in[3];
    float* out = (float*)d_out;

    enc_kernel<<<NROWS / 16, 256>>>(x, W, b, out);
    cudaFuncSetAttribute(dgm_kernel, cudaFuncAttributeMaxDynamicSharedMemorySize, SM_BYTES);
    dgm_kernel<<<dim3(NGRAPH, NNODE / TI), 256, SM_BYTES>>>(out, temp);
}

// round 6
// speedup vs baseline: 1.6220x; 1.0244x over previous
#include <cuda_runtime.h>
#include <math.h>
#include <stdint.h>

#define NGRAPH 32
#define NNODE  1024
#define CDIM   64
#define KTOP   16
#define NROWS  (NGRAPH * NNODE)            // 32768
#define OUT_ELEMS (NROWS * CDIM)           // 2097152
#define ROWS_OFF  OUT_ELEMS
#define COLS_OFF  (OUT_ELEMS + NROWS * KTOP)

__device__ float g_sq[NROWS];

// ---------------------------------------------------------------------------
// Encoder + fused row squared-norms.  4x4 register tile, 64-row blocks.
// out[32768,64] = x[32768,128] @ W[128,64] + b ; g_sq[r] = sum_c out[r,c]^2
// ---------------------------------------------------------------------------
#define ENC_WT   0                          // [64][132] floats = 8448
#define ENC_X    8448                       // [64][128] floats = 8192
#define ENC_TOTF 16640
#define ENC_BYTES (ENC_TOTF * 4)            // 66560 B

__global__ void __launch_bounds__(256) enc_kernel(const float* __restrict__ x,
                                                  const float* __restrict__ W,
                                                  const float* __restrict__ b,
                                                  float* __restrict__ out) {
    extern __shared__ float esm[];
    float* sWt = esm + ENC_WT;   // W transposed [c][k], stride 132 (33 16B-units)
    float* sX  = esm + ENC_X;    // 64-row strip of x, stride 128
    int tid = threadIdx.x;
    int i0 = blockIdx.x * 64;

    for (int idx = tid; idx < 128 * 64; idx += 256) {
        int k = idx >> 6, c = idx & 63;
        sWt[c * 132 + k] = W[idx];
    }
    for (int idx = tid; idx < 64 * 128 / 4; idx += 256) {
        ((float4*)sX)[idx] = ((const float4*)(x + (size_t)i0 * 128))[idx];
    }
    __syncthreads();

    int cgrp = tid & 15;         // columns c = cgrp + 16*cc  (stride-16 split)
    int rgrp = tid >> 4;         // rows    r = i0 + rgrp*4 + rr
    float acc[4][4];
#pragma unroll
    for (int rr = 0; rr < 4; rr++)
#pragma unroll
        for (int cc = 0; cc < 4; cc++) acc[rr][cc] = 0.f;

#pragma unroll
    for (int k4 = 0; k4 < 32; k4++) {
        float4 wv[4];
#pragma unroll
        for (int cc = 0; cc < 4; cc++)
            wv[cc] = *(const float4*)(sWt + (cgrp + 16 * cc) * 132 + k4 * 4);
#pragma unroll
        for (int rr = 0; rr < 4; rr++) {
            float4 xv = *(const float4*)(sX + (rgrp * 4 + rr) * 128 + k4 * 4);
#pragma unroll
            for (int cc = 0; cc < 4; cc++) {
                acc[rr][cc] += xv.x * wv[cc].x + xv.y * wv[cc].y
                             + xv.z * wv[cc].z + xv.w * wv[cc].w;
            }
        }
    }

    float bb[4];
#pragma unroll
    for (int cc = 0; cc < 4; cc++) bb[cc] = b[cgrp + 16 * cc];

    float sqp[4] = {0.f, 0.f, 0.f, 0.f};
#pragma unroll
    for (int rr = 0; rr < 4; rr++) {
        int r = i0 + rgrp * 4 + rr;
#pragma unroll
        for (int cc = 0; cc < 4; cc++) {
            float val = acc[rr][cc] + bb[cc];
            out[(size_t)r * 64 + cgrp + 16 * cc] = val;
            sqp[rr] += val * val;
        }
    }
    // reduce over the 16 cgrp lanes (lanes xor 1,2,4,8 stay within each half-warp)
#pragma unroll
    for (int rr = 0; rr < 4; rr++) {
#pragma unroll
        for (int o = 8; o; o >>= 1) sqp[rr] += __shfl_xor_sync(0xffffffffu, sqp[rr], o);
    }
    if (cgrp == 0) {
#pragma unroll
        for (int rr = 0; rr < 4; rr++) g_sq[i0 + rgrp * 4 + rr] = sqp[rr];
    }
}

// ---------------------------------------------------------------------------
// JAX threefry2x32, key (0,1), partitionable counter mode (verified R3).
// ---------------------------------------------------------------------------
__device__ __forceinline__ uint32_t threefry_bits_k01(uint32_t e) {
    const uint32_t ks0 = 0u, ks1 = 1u, ks2 = 0x1BD11BDBu;
    uint32_t x0 = 0u + ks0;
    uint32_t x1 = e + ks1;
#define TF_ROUND(r) { x0 += x1; x1 = __funnelshift_l(x1, x1, (r)); x1 ^= x0; }
    TF_ROUND(13) TF_ROUND(15) TF_ROUND(26) TF_ROUND(6)
    x0 += ks1; x1 += ks2 + 1u;
    TF_ROUND(17) TF_ROUND(29) TF_ROUND(16) TF_ROUND(24)
    x0 += ks2; x1 += ks0 + 2u;
    TF_ROUND(13) TF_ROUND(15) TF_ROUND(26) TF_ROUND(6)
    x0 += ks0; x1 += ks1 + 3u;
    TF_ROUND(17) TF_ROUND(29) TF_ROUND(16) TF_ROUND(24)
    x0 += ks1; x1 += ks2 + 4u;
    TF_ROUND(13) TF_ROUND(15) TF_ROUND(26) TF_ROUND(6)
    x0 += ks2; x1 += ks0 + 5u;
#undef TF_ROUND
    return x0 ^ x1;
}

// ---------------------------------------------------------------------------
// Fused: pairwise dist + logits + gumbel + top-16 per row.
// Block = (graph g, 32-row i-strip), 256 threads, grid (32, 32), 3 blocks/SM.
// Hash pass is batched 8-wide for ILP; integer mantissa prefilter.
// ---------------------------------------------------------------------------
#define TI 32
#define TJ 128
#define CAP 96
#define SSTRIDE 68    // floats; odd 16B-unit stride -> conflict-free LDS.128
#define THR0 2.0f     // phantom init threshold (v_16th of 1024 >> 2 w.p. ~1)
#define LGMAX 1.001f  // rigorous upper bound on exp(-T*d) incl. rounding

// shared layout in floats
#define SM_SA     0                        // [32][68]   = 2176
#define SM_SB     2176                     // [128][68]  = 8704
#define SM_SQI    10880                    // [32]
#define SM_SQJ    10912                    // [128]
#define SM_THR    11040                    // [32]
#define SM_CUTB   11072                    // [32] uint
#define SM_TOPV   11104                    // [32][16]   = 512
#define SM_CANDV  11616                    // [32][96]   = 3072
#define SM_CANDI  14688                    // [32][96] int
#define SM_TOPI   17760                    // [32][16] int
#define SM_CNT    18272                    // [32] int
#define SM_TOTALF 18304
#define SM_BYTES  (SM_TOTALF * 4)          // 73216 B -> 3 blocks/SM

__device__ __forceinline__ uint32_t cut_bits_from_thr(float thr) {
    // v > thr requires gumbel > thr - LGMAX, i.e. f > exp(-exp(-(thr-LGMAX))).
    float fcut = __expf(-__expf(-(thr - LGMAX))) - 2e-7f;
    return __float_as_uint(1.0f + fcut);
}

__global__ void __launch_bounds__(256, 3) dgm_kernel(float* __restrict__ buf,
                                                     const float* __restrict__ tptr) {
    extern __shared__ float sm[];
    float* sA    = sm + SM_SA;
    float* sB    = sm + SM_SB;
    float* sqI   = sm + SM_SQI;
    float* sqJ   = sm + SM_SQJ;
    float* thr   = sm + SM_THR;
    uint32_t* cutb = (uint32_t*)(sm + SM_CUTB);
    float* topV  = sm + SM_TOPV;
    float* candV = sm + SM_CANDV;
    int*   candI = (int*)(sm + SM_CANDI);
    int*   topI  = (int*)(sm + SM_TOPI);
    int*   cnt   = (int*)(sm + SM_CNT);

    const float* h = buf;
    int tid = threadIdx.x;
    int g   = blockIdx.x;
    int i0  = blockIdx.y * TI;
    int gbase = g * NNODE;

    // ---- init ----
    for (int idx = tid; idx < TI * 16; idx += 256) {
        int r = idx >> 4, k4 = idx & 15;
        *(float4*)(sA + r * SSTRIDE + k4 * 4) =
            ((const float4*)(h + (size_t)(gbase + i0 + r) * 64))[k4];
    }
    if (tid < TI) {
        sqI[tid] = g_sq[gbase + i0 + tid];
        thr[tid] = THR0;
        cutb[tid] = cut_bits_from_thr(THR0);
        cnt[tid] = 0;
    }
    for (int idx = tid; idx < TI * KTOP; idx += 256) { topV[idx] = -INFINITY; topI[idx] = 0; }

    float nT = -(*tptr);
    int tx = tid & 31;      // j-cols: tx + 32*jj
    int ty = tid >> 5;      // i-rows: ty*4 + ii

    for (int jt = 0; jt < NNODE / TJ; jt++) {
        int j0 = jt * TJ;
        for (int idx = tid; idx < TJ * 16; idx += 256) {
            int r = idx >> 4, k4 = idx & 15;
            *(float4*)(sB + r * SSTRIDE + k4 * 4) =
                ((const float4*)(h + (size_t)(gbase + j0 + r) * 64))[k4];
        }
        if (tid < TJ) sqJ[tid] = g_sq[gbase + j0 + tid];
        __syncthreads();

        // ---- 4x4 register-tiled dots ----
        float acc[4][4];
#pragma unroll
        for (int ii = 0; ii < 4; ii++)
#pragma unroll
            for (int jj = 0; jj < 4; jj++) acc[ii][jj] = 0.f;

        const float* pA = sA + (ty * 4) * SSTRIDE;
        const float* pB = sB + tx * SSTRIDE;
#pragma unroll
        for (int k4 = 0; k4 < 16; k4++) {
            float4 jf0 = *(const float4*)(pB + (0 * 32) * SSTRIDE + k4 * 4);
            float4 jf1 = *(const float4*)(pB + (1 * 32) * SSTRIDE + k4 * 4);
            float4 jf2 = *(const float4*)(pB + (2 * 32) * SSTRIDE + k4 * 4);
            float4 jf3 = *(const float4*)(pB + (3 * 32) * SSTRIDE + k4 * 4);
#pragma unroll
            for (int ii = 0; ii < 4; ii++) {
                float4 af = *(const float4*)(pA + ii * SSTRIDE + k4 * 4);
                acc[ii][0] += af.x * jf0.x + af.y * jf0.y + af.z * jf0.z + af.w * jf0.w;
                acc[ii][1] += af.x * jf1.x + af.y * jf1.y + af.z * jf1.z + af.w * jf1.w;
                acc[ii][2] += af.x * jf2.x + af.y * jf2.y + af.z * jf2.z + af.w * jf2.w;
                acc[ii][3] += af.x * jf3.x + af.y * jf3.y + af.z * jf3.z + af.w * jf3.w;
            }
        }

        // ---- per-row scalars to registers ----
        float thrR[4], sqi[4], sqj[4];
        uint32_t cutM[4];
#pragma unroll
        for (int ii = 0; ii < 4; ii++) {
            thrR[ii] = thr[ty * 4 + ii];
            sqi[ii]  = sqI[ty * 4 + ii];
            cutM[ii] = cutb[ty * 4 + ii] & 0x007fffffu;   // mantissa-only cutoff
        }
#pragma unroll
        for (int jj = 0; jj < 4; jj++) sqj[jj] = sqJ[jj * 32 + tx];

        uint32_t e0 = ((uint32_t)g << 20) + ((uint32_t)(i0 + ty * 4) << 10)
                      + (uint32_t)(j0 + tx);

        // ---- 8-wide batched hash pass + filter, twice ----
#pragma unroll
        for (int half = 0; half < 2; half++) {
            uint32_t bts[8];
#pragma unroll
            for (int u = 0; u < 8; u++) {
                int ii = half * 2 + (u >> 2);
                int jj = u & 3;
                bts[u] = threefry_bits_k01(e0 + ((uint32_t)ii << 10) + ((uint32_t)jj << 5));
            }
#pragma unroll
            for (int u = 0; u < 8; u++) {
                int ii = half * 2 + (u >> 2);
                int jj = u & 3;
                uint32_t mant = bts[u] >> 9;
                if (mant > cutM[ii]) {
                    int li = ty * 4 + ii;
                    float f   = __uint_as_float(mant | 0x3f800000u) - 1.0f;
                    float gum = -__logf(-log1pf(f - 1.0f));
                    float s   = __fadd_rn(sqi[ii], sqj[jj]);
                    float d   = __fadd_rn(s, -__fmul_rn(2.0f, acc[ii][jj]));
                    float lg  = __expf(__fmul_rn(nT, d));
                    float v   = lg + gum;
                    if (v > thrR[ii]) {
                        int p = atomicAdd(&cnt[li], 1);
                        if (p < CAP) {
                            candV[li * CAP + p] = v;
                            candI[li * CAP + p] = j0 + jj * 32 + tx;
                        }
                    }
                }
            }
        }
        __syncthreads();

        // ---- leaders merge candidates, raise threshold + bit cutoff ----
        if (tid < TI) {
            int r = tid, c = min(cnt[r], CAP);
            float* tv = topV + r * KTOP;
            int*   ti = topI + r * KTOP;
            for (int m = 0; m < c; m++) {
                float v = candV[r * CAP + m];
                if (v > tv[KTOP - 1]) {
                    int id = candI[r * CAP + m];
                    int p = KTOP - 1;
                    while (p > 0 && tv[p - 1] < v) {
                        tv[p] = tv[p - 1]; ti[p] = ti[p - 1]; p--;
                    }
                    tv[p] = v; ti[p] = id;
                }
            }
            cnt[r] = 0;
            float nthr = fmaxf(tv[KTOP - 1], THR0);
            thr[r] = nthr;
            cutb[r] = cut_bits_from_thr(nthr);
        }
        __syncthreads();
    }

    // ---- write edges (indices as float) ----
    if (tid < TI) {
        int grow = gbase + i0 + tid;
        size_t base = (size_t)grow * KTOP;
        float rowv = (float)grow;
#pragma unroll
        for (int k = 0; k < KTOP; k++) {
            buf[ROWS_OFF + base + k] = rowv;
            buf[COLS_OFF + base + k] = (float)(gbase + topI[tid * KTOP + k]);
        }
    }
}

// ---------------------------------------------------------------------------
extern "C" void kernel_launch(void* const* d_in, const int* in_sizes, int n_in,
                              void* d_out, int out_size) {
    const float* x    = (const float*)d_in[0];
    const float* W    = (const float*)d_in[1];
    const float* b    = (const float*)d_in[2];
    const float* temp = (const float*)d_in[3];
    float* out = (float*)d_out;

    cudaFuncSetAttribute(enc_kernel, cudaFuncAttributeMaxDynamicSharedMemorySize, ENC_BYTES);
    enc_kernel<<<NROWS / 64, 256, ENC_BYTES>>>(x, W, b, out);
    cudaFuncSetAttribute(dgm_kernel, cudaFuncAttributeMaxDynamicSharedMemorySize, SM_BYTES);
    dgm_kernel<<<dim3(NGRAPH, NNODE / TI), 256, SM_BYTES>>>(out, temp);
}

// round 7
// speedup vs baseline: 1.7932x; 1.1055x over previous
#include <cuda_runtime.h>
#include <math.h>
#include <stdint.h>

#define NGRAPH 32
#define NNODE  1024
#define CDIM   64
#define KTOP   16
#define NROWS  (NGRAPH * NNODE)            // 32768
#define OUT_ELEMS (NROWS * CDIM)           // 2097152
#define ROWS_OFF  OUT_ELEMS
#define COLS_OFF  (OUT_ELEMS + NROWS * KTOP)

__device__ float g_sq[NROWS];

// ---------------------------------------------------------------------------
// Encoder + fused row squared-norms.  4x4 register tile, 64-row blocks.
// ---------------------------------------------------------------------------
#define ENC_WT   0                          // [64][132] floats = 8448
#define ENC_X    8448                       // [64][128] floats = 8192
#define ENC_TOTF 16640
#define ENC_BYTES (ENC_TOTF * 4)

__global__ void __launch_bounds__(256) enc_kernel(const float* __restrict__ x,
                                                  const float* __restrict__ W,
                                                  const float* __restrict__ b,
                                                  float* __restrict__ out) {
    extern __shared__ float esm[];
    float* sWt = esm + ENC_WT;
    float* sX  = esm + ENC_X;
    int tid = threadIdx.x;
    int i0 = blockIdx.x * 64;

    for (int idx = tid; idx < 128 * 64; idx += 256) {
        int k = idx >> 6, c = idx & 63;
        sWt[c * 132 + k] = W[idx];
    }
    for (int idx = tid; idx < 64 * 128 / 4; idx += 256) {
        ((float4*)sX)[idx] = ((const float4*)(x + (size_t)i0 * 128))[idx];
    }
    __syncthreads();

    int cgrp = tid & 15;
    int rgrp = tid >> 4;
    float acc[4][4];
#pragma unroll
    for (int rr = 0; rr < 4; rr++)
#pragma unroll
        for (int cc = 0; cc < 4; cc++) acc[rr][cc] = 0.f;

#pragma unroll
    for (int k4 = 0; k4 < 32; k4++) {
        float4 wv[4];
#pragma unroll
        for (int cc = 0; cc < 4; cc++)
            wv[cc] = *(const float4*)(sWt + (cgrp + 16 * cc) * 132 + k4 * 4);
#pragma unroll
        for (int rr = 0; rr < 4; rr++) {
            float4 xv = *(const float4*)(sX + (rgrp * 4 + rr) * 128 + k4 * 4);
#pragma unroll
            for (int cc = 0; cc < 4; cc++) {
                acc[rr][cc] += xv.x * wv[cc].x + xv.y * wv[cc].y
                             + xv.z * wv[cc].z + xv.w * wv[cc].w;
            }
        }
    }

    float bb[4];
#pragma unroll
    for (int cc = 0; cc < 4; cc++) bb[cc] = b[cgrp + 16 * cc];

    float sqp[4] = {0.f, 0.f, 0.f, 0.f};
#pragma unroll
    for (int rr = 0; rr < 4; rr++) {
        int r = i0 + rgrp * 4 + rr;
#pragma unroll
        for (int cc = 0; cc < 4; cc++) {
            float val = acc[rr][cc] + bb[cc];
            out[(size_t)r * 64 + cgrp + 16 * cc] = val;
            sqp[rr] += val * val;
        }
    }
#pragma unroll
    for (int rr = 0; rr < 4; rr++) {
#pragma unroll
        for (int o = 8; o; o >>= 1) sqp[rr] += __shfl_xor_sync(0xffffffffu, sqp[rr], o);
    }
    if (cgrp == 0) {
#pragma unroll
        for (int rr = 0; rr < 4; rr++) g_sq[i0 + rgrp * 4 + rr] = sqp[rr];
    }
}

// ---------------------------------------------------------------------------
// JAX threefry2x32, key (0,1), partitionable counter mode (verified R3).
// ---------------------------------------------------------------------------
__device__ __forceinline__ uint32_t threefry_bits_k01(uint32_t e) {
    const uint32_t ks0 = 0u, ks1 = 1u, ks2 = 0x1BD11BDBu;
    uint32_t x0 = 0u + ks0;
    uint32_t x1 = e + ks1;
#define TF_ROUND(r) { x0 += x1; x1 = __funnelshift_l(x1, x1, (r)); x1 ^= x0; }
    TF_ROUND(13) TF_ROUND(15) TF_ROUND(26) TF_ROUND(6)
    x0 += ks1; x1 += ks2 + 1u;
    TF_ROUND(17) TF_ROUND(29) TF_ROUND(16) TF_ROUND(24)
    x0 += ks2; x1 += ks0 + 2u;
    TF_ROUND(13) TF_ROUND(15) TF_ROUND(26) TF_ROUND(6)
    x0 += ks0; x1 += ks1 + 3u;
    TF_ROUND(17) TF_ROUND(29) TF_ROUND(16) TF_ROUND(24)
    x0 += ks1; x1 += ks2 + 4u;
    TF_ROUND(13) TF_ROUND(15) TF_ROUND(26) TF_ROUND(6)
    x0 += ks2; x1 += ks0 + 5u;
#undef TF_ROUND
    return x0 ^ x1;
}

// Packed dual-FMA (sm_103a f32x2 pipe): d.lo += a.lo*b.lo, d.hi += a.hi*b.hi
__device__ __forceinline__ void ffma2(unsigned long long& d,
                                      unsigned long long a,
                                      unsigned long long b) {
    asm("fma.rn.f32x2 %0, %1, %2, %0;" : "+l"(d) : "l"(a), "l"(b));
}

// ---------------------------------------------------------------------------
// Fused: pairwise dist + logits + gumbel + top-16 per row.
// Block = (graph g, 32-row i-strip), 256 threads, grid (32, 32), 4 blocks/SM.
// TJ=64 j-tiles; f32x2 packed dot; integer mantissa prefilter.
// ---------------------------------------------------------------------------
#define TI 32
#define TJ 64
#define CAP 64
#define SSTRIDE 68    // floats; odd 16B-unit stride -> conflict-free LDS.128
#define THR0 2.0f
#define LGMAX 1.001f

// shared layout in floats
#define SM_SA     0                        // [32][68]  = 2176
#define SM_SB     2176                     // [64][68]  = 4352
#define SM_SQI    6528                     // [32]
#define SM_SQJ    6560                     // [64]
#define SM_THR    6624                     // [32]
#define SM_CUTB   6656                     // [32] uint
#define SM_TOPV   6688                     // [32][16]  = 512
#define SM_CANDV  7200                     // [32][64]  = 2048
#define SM_CANDI  9248                     // [32][64] int
#define SM_TOPI   11296                    // [32][16] int
#define SM_CNT    11808                    // [32] int
#define SM_TOTALF 11840
#define SM_BYTES  (SM_TOTALF * 4)          // 47360 B -> 4 blocks/SM

__device__ __forceinline__ uint32_t cut_bits_from_thr(float thr) {
    float fcut = __expf(-__expf(-(thr - LGMAX))) - 2e-7f;
    return __float_as_uint(1.0f + fcut);
}

__global__ void __launch_bounds__(256, 4) dgm_kernel(float* __restrict__ buf,
                                                     const float* __restrict__ tptr) {
    extern __shared__ float sm[];
    float* sA    = sm + SM_SA;
    float* sB    = sm + SM_SB;
    float* sqI   = sm + SM_SQI;
    float* sqJ   = sm + SM_SQJ;
    float* thr   = sm + SM_THR;
    uint32_t* cutb = (uint32_t*)(sm + SM_CUTB);
    float* topV  = sm + SM_TOPV;
    float* candV = sm + SM_CANDV;
    int*   candI = (int*)(sm + SM_CANDI);
    int*   topI  = (int*)(sm + SM_TOPI);
    int*   cnt   = (int*)(sm + SM_CNT);

    const float* h = buf;
    int tid = threadIdx.x;
    int g   = blockIdx.x;
    int i0  = blockIdx.y * TI;
    int gbase = g * NNODE;

    // ---- init ----
    for (int idx = tid; idx < TI * 16; idx += 256) {
        int r = idx >> 4, k4 = idx & 15;
        *(float4*)(sA + r * SSTRIDE + k4 * 4) =
            ((const float4*)(h + (size_t)(gbase + i0 + r) * 64))[k4];
    }
    if (tid < TI) {
        sqI[tid] = g_sq[gbase + i0 + tid];
        thr[tid] = THR0;
        cutb[tid] = cut_bits_from_thr(THR0);
        cnt[tid] = 0;
    }
    for (int idx = tid; idx < TI * KTOP; idx += 256) { topV[idx] = -INFINITY; topI[idx] = 0; }

    float nT = -(*tptr);
    int tx = tid & 31;      // j-cols: tx + 32*jj, jj in {0,1}
    int ty = tid >> 5;      // i-rows: ty*4 + ii

    for (int jt = 0; jt < NNODE / TJ; jt++) {
        int j0 = jt * TJ;
        for (int idx = tid; idx < TJ * 16; idx += 256) {
            int r = idx >> 4, k4 = idx & 15;
            *(float4*)(sB + r * SSTRIDE + k4 * 4) =
                ((const float4*)(h + (size_t)(gbase + j0 + r) * 64))[k4];
        }
        if (tid < TJ) sqJ[tid] = g_sq[gbase + j0 + tid];
        __syncthreads();

        // ---- 4x2 register-tiled dots, packed f32x2 FMA ----
        unsigned long long acc2[4][2];
#pragma unroll
        for (int ii = 0; ii < 4; ii++) { acc2[ii][0] = 0ull; acc2[ii][1] = 0ull; }

        const float* pA = sA + (ty * 4) * SSTRIDE;
        const float* pB = sB + tx * SSTRIDE;
#pragma unroll
        for (int k4 = 0; k4 < 16; k4++) {
            ulonglong2 b0 = *(const ulonglong2*)(pB + k4 * 4);
            ulonglong2 b1 = *(const ulonglong2*)(pB + 32 * SSTRIDE + k4 * 4);
#pragma unroll
            for (int ii = 0; ii < 4; ii++) {
                ulonglong2 a = *(const ulonglong2*)(pA + ii * SSTRIDE + k4 * 4);
                ffma2(acc2[ii][0], a.x, b0.x);
                ffma2(acc2[ii][0], a.y, b0.y);
                ffma2(acc2[ii][1], a.x, b1.x);
                ffma2(acc2[ii][1], a.y, b1.y);
            }
        }

        // ---- per-row scalars ----
        float thrR[4], sqi[4], sqj[2];
        uint32_t cutM[4];
#pragma unroll
        for (int ii = 0; ii < 4; ii++) {
            thrR[ii] = thr[ty * 4 + ii];
            sqi[ii]  = sqI[ty * 4 + ii];
            cutM[ii] = cutb[ty * 4 + ii] & 0x007fffffu;
        }
        sqj[0] = sqJ[tx];
        sqj[1] = sqJ[32 + tx];

        uint32_t e0 = ((uint32_t)g << 20) + ((uint32_t)(i0 + ty * 4) << 10)
                      + (uint32_t)(j0 + tx);

        // ---- batched hashes + filter ----
        uint32_t bts[8];
#pragma unroll
        for (int u = 0; u < 8; u++) {
            int ii = u >> 1, jj = u & 1;
            bts[u] = threefry_bits_k01(e0 + ((uint32_t)ii << 10) + ((uint32_t)jj << 5));
        }
#pragma unroll
        for (int u = 0; u < 8; u++) {
            int ii = u >> 1, jj = u & 1;
            uint32_t mant = bts[u] >> 9;
            if (mant > cutM[ii]) {
                int li = ty * 4 + ii;
                unsigned long long av = acc2[ii][jj];
                float dot = __uint_as_float((uint32_t)av)
                          + __uint_as_float((uint32_t)(av >> 32));
                float f   = __uint_as_float(mant | 0x3f800000u) - 1.0f;
                float gum = -__logf(-log1pf(f - 1.0f));
                float s   = __fadd_rn(sqi[ii], sqj[jj]);
                float d   = __fadd_rn(s, -__fmul_rn(2.0f, dot));
                float lg  = __expf(__fmul_rn(nT, d));
                float v   = lg + gum;
                if (v > thrR[ii]) {
                    int p = atomicAdd(&cnt[li], 1);
                    if (p < CAP) {
                        candV[li * CAP + p] = v;
                        candI[li * CAP + p] = j0 + jj * 32 + tx;
                    }
                }
            }
        }
        __syncthreads();

        // ---- leaders merge candidates, raise threshold + bit cutoff ----
        if (tid < TI) {
            int r = tid, c = min(cnt[r], CAP);
            float* tv = topV + r * KTOP;
            int*   ti = topI + r * KTOP;
            for (int m = 0; m < c; m++) {
                float v = candV[r * CAP + m];
                if (v > tv[KTOP - 1]) {
                    int id = candI[r * CAP + m];
                    int p = KTOP - 1;
                    while (p > 0 && tv[p - 1] < v) {
                        tv[p] = tv[p - 1]; ti[p] = ti[p - 1]; p--;
                    }
                    tv[p] = v; ti[p] = id;
                }
            }
            cnt[r] = 0;
            float nthr = fmaxf(tv[KTOP - 1], THR0);
            thr[r] = nthr;
            cutb[r] = cut_bits_from_thr(nthr);
        }
        __syncthreads();
    }

    // ---- write edges (indices as float) ----
    if (tid < TI) {
        int grow = gbase + i0 + tid;
        size_t base = (size_t)grow * KTOP;
        float rowv = (float)grow;
#pragma unroll
        for (int k = 0; k < KTOP; k++) {
            buf[ROWS_OFF + base + k] = rowv;
            buf[COLS_OFF + base + k] = (float)(gbase + topI[tid * KTOP + k]);
        }
    }
}

// ---------------------------------------------------------------------------
extern "C" void kernel_launch(void* const* d_in, const int* in_sizes, int n_in,
                              void* d_out, int out_size) {
    const float* x    = (const float*)d_in[0];
    const float* W    = (const float*)d_in[1];
    const float* b    = (const float*)d_in[2];
    const float* temp = (const float*)d_in[3];
    float* out = (float*)d_out;

    cudaFuncSetAttribute(enc_kernel, cudaFuncAttributeMaxDynamicSharedMemorySize, ENC_BYTES);
    enc_kernel<<<NROWS / 64, 256, ENC_BYTES>>>(x, W, b, out);
    cudaFuncSetAttribute(dgm_kernel, cudaFuncAttributeMaxDynamicSharedMemorySize, SM_BYTES);
    dgm_kernel<<<dim3(NGRAPH, NNODE / TI), 256, SM_BYTES>>>(out, temp);
}